// round 1
// baseline (speedup 1.0000x reference)
#include <cuda_runtime.h>
#include <cuda_bf16.h>
#include <math.h>

#define NN 50000
#define NE 500000
#define FN 7
#define FE 8
#define DD 64
#define HH 128
#define EIN 136          // 2*DD + FE
#define UIN 192          // DD + HH
#define LL 3
#define EPT 8            // edges per block-iteration

// ---------------- scratch (no allocations allowed) ----------------
__device__ float g_x[NN * DD];      // node state
__device__ float g_agg[NN * HH];    // scatter target
__device__ float g_cnt[NN];         // in-degree counts

// ---------------- utility kernels ----------------
__global__ void zero_kernel(float* __restrict__ p, int n4) {
    int i = blockIdx.x * blockDim.x + threadIdx.x;
    if (i < n4) ((float4*)p)[i] = make_float4(0.f, 0.f, 0.f, 0.f);
}

__global__ void count_kernel(const int* __restrict__ dst) {
    int e = blockIdx.x * blockDim.x + threadIdx.x;
    if (e < NE) atomicAdd(&g_cnt[dst[e]], 1.0f);
}

__global__ void embed_kernel(const float* __restrict__ nf,
                             const float* __restrict__ W,
                             const float* __restrict__ b) {
    int idx = blockIdx.x * blockDim.x + threadIdx.x;  // over NN*DD
    if (idx >= NN * DD) return;
    int n = idx >> 6, d = idx & 63;
    float acc = b[d];
#pragma unroll
    for (int f = 0; f < FN; f++) acc += nf[n * FN + f] * W[f * DD + d];
    g_x[idx] = fmaxf(acc, 0.f);
}

// ---------------- fused edge message MLP + scatter ----------------
// smem: W1[136*128] W2[128*128] b1[128] b2[128] in[EPT*136] h[EPT*128]
#define MSG_SMEM ((EIN*HH + HH*HH + 2*HH + EPT*EIN + EPT*HH) * 4)

__global__ void __launch_bounds__(256, 1)
msg_kernel(const float* __restrict__ ea,
           const int* __restrict__ src, const int* __restrict__ dst,
           const float* __restrict__ W1, const float* __restrict__ b1,
           const float* __restrict__ W2, const float* __restrict__ b2) {
    extern __shared__ float s[];
    float* sW1 = s;                  // 17408
    float* sW2 = sW1 + EIN * HH;     // 16384
    float* sB1 = sW2 + HH * HH;      // 128
    float* sB2 = sB1 + HH;           // 128
    float* sIn = sB2 + HH;           // EPT*136
    float* sH  = sIn + EPT * EIN;    // EPT*128

    int tid = threadIdx.x;
    for (int i = tid; i < EIN * HH; i += 256) sW1[i] = W1[i];
    for (int i = tid; i < HH * HH; i += 256) sW2[i] = W2[i];
    if (tid < HH) { sB1[tid] = b1[tid]; sB2[tid] = b2[tid]; }
    __syncthreads();

    const int j  = tid & (HH - 1);
    const int eh = tid >> 7;   // 0/1: which edge of each pair

    for (int e0 = blockIdx.x * EPT; e0 < NE; e0 += gridDim.x * EPT) {
        // ---- stage edge inputs [x[src] | x[dst] | edge_attr] ----
#pragma unroll
        for (int e = 0; e < EPT; e++) {
            int ge = e0 + e;
            bool ok = ge < NE;
            int sN = ok ? src[ge] : 0;
            int dN = ok ? dst[ge] : 0;
            if (tid < DD)            sIn[e * EIN + tid] = ok ? g_x[sN * DD + tid] : 0.f;
            else if (tid < 2 * DD)   sIn[e * EIN + tid] = ok ? g_x[dN * DD + (tid - DD)] : 0.f;
            else if (tid < EIN)      sIn[e * EIN + tid] = ok ? ea[ge * FE + (tid - 2 * DD)] : 0.f;
        }
        __syncthreads();

        // ---- h = relu(in @ W1 + b1) : thread (eh,j) does edges eh,eh+2,eh+4,eh+6 ----
        float acc[EPT / 2];
#pragma unroll
        for (int c = 0; c < EPT / 2; c++) acc[c] = sB1[j];
#pragma unroll
        for (int i = 0; i < EIN; i += 4) {
            float w0 = sW1[(i + 0) * HH + j];
            float w1 = sW1[(i + 1) * HH + j];
            float w2 = sW1[(i + 2) * HH + j];
            float w3 = sW1[(i + 3) * HH + j];
#pragma unroll
            for (int c = 0; c < EPT / 2; c++) {
                float4 v = *(const float4*)&sIn[(eh + 2 * c) * EIN + i];
                acc[c] += v.x * w0 + v.y * w1 + v.z * w2 + v.w * w3;
            }
        }
#pragma unroll
        for (int c = 0; c < EPT / 2; c++) sH[(eh + 2 * c) * HH + j] = fmaxf(acc[c], 0.f);
        __syncthreads();

        // ---- msg = h @ W2 + b2; scatter-add to agg[dst] ----
        float acc2[EPT / 2];
#pragma unroll
        for (int c = 0; c < EPT / 2; c++) acc2[c] = sB2[j];
#pragma unroll
        for (int i = 0; i < HH; i += 4) {
            float w0 = sW2[(i + 0) * HH + j];
            float w1 = sW2[(i + 1) * HH + j];
            float w2 = sW2[(i + 2) * HH + j];
            float w3 = sW2[(i + 3) * HH + j];
#pragma unroll
            for (int c = 0; c < EPT / 2; c++) {
                float4 v = *(const float4*)&sH[(eh + 2 * c) * HH + i];
                acc2[c] += v.x * w0 + v.y * w1 + v.z * w2 + v.w * w3;
            }
        }
#pragma unroll
        for (int c = 0; c < EPT / 2; c++) {
            int ge = e0 + eh + 2 * c;
            if (ge < NE) atomicAdd(&g_agg[dst[ge] * HH + j], acc2[c]);
        }
        __syncthreads();
    }
}

// ---------------- node update: mean-norm agg, MLP, residual, LayerNorm ----------------
#define UPD_SMEM ((UIN*DD + 3*DD + 2*UIN + 2*DD) * 4)

__global__ void __launch_bounds__(128)
upd_kernel(const float* __restrict__ W, const float* __restrict__ b,
           const float* __restrict__ lg, const float* __restrict__ lb) {
    extern __shared__ float s[];
    float* sW  = s;                  // 192*64
    float* sB  = sW + UIN * DD;      // 64
    float* sG  = sB + DD;            // 64
    float* sLB = sG + DD;            // 64
    float* sIn = sLB + DD;           // 2*192
    float* sOut = sIn + 2 * UIN;     // 2*64

    int tid = threadIdx.x;
    for (int i = tid; i < UIN * DD; i += 128) sW[i] = W[i];
    if (tid < DD) { sB[tid] = b[tid]; sG[tid] = lg[tid]; sLB[tid] = lb[tid]; }
    __syncthreads();

    int ln = tid >> 6;     // local node 0/1
    int d  = tid & 63;

    for (int n0 = blockIdx.x * 2; n0 < NN; n0 += gridDim.x * 2) {
        int n = n0 + ln;
        bool ok = n < NN;
        float inv = ok ? 1.f / (g_cnt[n] + 1e-6f) : 0.f;
        if (ok) {
            sIn[ln * UIN + d]       = g_x[n * DD + d];
            sIn[ln * UIN + 64 + d]  = g_agg[n * HH + d] * inv;
            sIn[ln * UIN + 128 + d] = g_agg[n * HH + 64 + d] * inv;
        }
        __syncthreads();

        float acc = sB[d];
#pragma unroll
        for (int k = 0; k < UIN; k += 4) {
            float4 v = *(const float4*)&sIn[ln * UIN + k];
            acc += v.x * sW[(k + 0) * DD + d] + v.y * sW[(k + 1) * DD + d]
                 + v.z * sW[(k + 2) * DD + d] + v.w * sW[(k + 3) * DD + d];
        }
        float out = sIn[ln * UIN + d] + fmaxf(acc, 0.f);
        sOut[ln * DD + d] = out;
        __syncthreads();

        float mu = 0.f;
#pragma unroll
        for (int k = 0; k < DD; k++) mu += sOut[ln * DD + k];
        mu *= (1.f / DD);
        float m2 = 0.f;
#pragma unroll
        for (int k = 0; k < DD; k++) { float v = sOut[ln * DD + k] - mu; m2 += v * v; }
        m2 *= (1.f / DD);
        if (ok) g_x[n * DD + d] = (out - mu) * rsqrtf(m2 + 1e-5f) * sG[d] + sLB[d];
        __syncthreads();
    }
}

// ---------------- edge predictor: 136 -> 128 -> 64 -> 1, tanh ----------------
#define PRED_SMEM ((EIN*HH + HH*DD + DD + HH + DD + EPT*EIN + EPT*HH + EPT*DD) * 4)

__global__ void __launch_bounds__(256, 2)
pred_kernel(const float* __restrict__ ea,
            const int* __restrict__ src, const int* __restrict__ dst,
            const float* __restrict__ W1, const float* __restrict__ b1,
            const float* __restrict__ W2, const float* __restrict__ b2,
            const float* __restrict__ W3, const float* __restrict__ b3,
            float* __restrict__ out) {
    extern __shared__ float s[];
    float* sW1 = s;                  // 136*128
    float* sW2 = sW1 + EIN * HH;     // 128*64
    float* sW3 = sW2 + HH * DD;      // 64
    float* sB1 = sW3 + DD;           // 128
    float* sB2 = sB1 + HH;           // 64
    float* sIn = sB2 + DD;           // EPT*136
    float* sH1 = sIn + EPT * EIN;    // EPT*128
    float* sH2 = sH1 + EPT * HH;     // EPT*64

    int tid = threadIdx.x;
    for (int i = tid; i < EIN * HH; i += 256) sW1[i] = W1[i];
    for (int i = tid; i < HH * DD; i += 256) sW2[i] = W2[i];
    if (tid < DD) sW3[tid] = W3[tid];
    if (tid < HH) sB1[tid] = b1[tid];
    if (tid < DD) sB2[tid] = b2[tid];
    __syncthreads();

    const int j  = tid & (HH - 1);
    const int eh = tid >> 7;
    const int q  = tid >> 6;        // 0..3 for phase 2
    const int j2 = tid & 63;
    const int wp = tid >> 5;        // warp 0..7 for phase 3
    const int lane = tid & 31;
    const float bias3 = b3[0];

    for (int e0 = blockIdx.x * EPT; e0 < NE; e0 += gridDim.x * EPT) {
#pragma unroll
        for (int e = 0; e < EPT; e++) {
            int ge = e0 + e;
            bool ok = ge < NE;
            int sN = ok ? src[ge] : 0;
            int dN = ok ? dst[ge] : 0;
            if (tid < DD)            sIn[e * EIN + tid] = ok ? g_x[sN * DD + tid] : 0.f;
            else if (tid < 2 * DD)   sIn[e * EIN + tid] = ok ? g_x[dN * DD + (tid - DD)] : 0.f;
            else if (tid < EIN)      sIn[e * EIN + tid] = ok ? ea[ge * FE + (tid - 2 * DD)] : 0.f;
        }
        __syncthreads();

        // h1 = relu(in @ W1 + b1)
        float acc[EPT / 2];
#pragma unroll
        for (int c = 0; c < EPT / 2; c++) acc[c] = sB1[j];
#pragma unroll
        for (int i = 0; i < EIN; i += 4) {
            float w0 = sW1[(i + 0) * HH + j];
            float w1 = sW1[(i + 1) * HH + j];
            float w2 = sW1[(i + 2) * HH + j];
            float w3 = sW1[(i + 3) * HH + j];
#pragma unroll
            for (int c = 0; c < EPT / 2; c++) {
                float4 v = *(const float4*)&sIn[(eh + 2 * c) * EIN + i];
                acc[c] += v.x * w0 + v.y * w1 + v.z * w2 + v.w * w3;
            }
        }
#pragma unroll
        for (int c = 0; c < EPT / 2; c++) sH1[(eh + 2 * c) * HH + j] = fmaxf(acc[c], 0.f);
        __syncthreads();

        // h2 = relu(h1 @ W2 + b2) : 4 groups of 64 channels, 2 edges each
        float a2[EPT / 4];
#pragma unroll
        for (int c = 0; c < EPT / 4; c++) a2[c] = sB2[j2];
#pragma unroll
        for (int i = 0; i < HH; i += 4) {
            float w0 = sW2[(i + 0) * DD + j2];
            float w1 = sW2[(i + 1) * DD + j2];
            float w2 = sW2[(i + 2) * DD + j2];
            float w3 = sW2[(i + 3) * DD + j2];
#pragma unroll
            for (int c = 0; c < EPT / 4; c++) {
                float4 v = *(const float4*)&sH1[(q + 4 * c) * HH + i];
                a2[c] += v.x * w0 + v.y * w1 + v.z * w2 + v.w * w3;
            }
        }
#pragma unroll
        for (int c = 0; c < EPT / 4; c++) sH2[(q + 4 * c) * DD + j2] = fmaxf(a2[c], 0.f);
        __syncthreads();

        // pred = tanh(h2 . W3 + b3) : one warp per edge
        {
            float v = sH2[wp * DD + lane] * sW3[lane]
                    + sH2[wp * DD + 32 + lane] * sW3[32 + lane];
#pragma unroll
            for (int o = 16; o; o >>= 1) v += __shfl_xor_sync(0xFFFFFFFFu, v, o);
            if (lane == 0) {
                int ge = e0 + wp;
                if (ge < NE) out[ge] = tanhf(v + bias3);
            }
        }
        __syncthreads();
    }
}

// ---------------- launch ----------------
extern "C" void kernel_launch(void* const* d_in, const int* in_sizes, int n_in,
                              void* d_out, int out_size) {
    const float* node_features = (const float*)d_in[0];
    const float* edge_attr     = (const float*)d_in[1];
    const float* embed_W       = (const float*)d_in[2];
    const float* embed_b       = (const float*)d_in[3];
    const float* msg_W1        = (const float*)d_in[4];
    const float* msg_b1        = (const float*)d_in[5];
    const float* msg_W2        = (const float*)d_in[6];
    const float* msg_b2        = (const float*)d_in[7];
    const float* upd_W         = (const float*)d_in[8];
    const float* upd_b         = (const float*)d_in[9];
    const float* ln_g          = (const float*)d_in[10];
    const float* ln_b          = (const float*)d_in[11];
    const float* pred_W1       = (const float*)d_in[12];
    const float* pred_b1       = (const float*)d_in[13];
    const float* pred_W2       = (const float*)d_in[14];
    const float* pred_b2       = (const float*)d_in[15];
    const float* pred_W3       = (const float*)d_in[16];
    const float* pred_b3       = (const float*)d_in[17];
    const int*   edge_index    = (const int*)d_in[18];
    float* out = (float*)d_out;

    const int* src = edge_index;
    const int* dst = edge_index + NE;

    cudaFuncSetAttribute(msg_kernel,  cudaFuncAttributeMaxDynamicSharedMemorySize, MSG_SMEM);
    cudaFuncSetAttribute(pred_kernel, cudaFuncAttributeMaxDynamicSharedMemorySize, PRED_SMEM);
    cudaFuncSetAttribute(upd_kernel,  cudaFuncAttributeMaxDynamicSharedMemorySize, UPD_SMEM);

    float* d_x;   cudaGetSymbolAddress((void**)&d_x,   g_x);
    float* d_agg; cudaGetSymbolAddress((void**)&d_agg, g_agg);
    float* d_cnt; cudaGetSymbolAddress((void**)&d_cnt, g_cnt);

    // counts
    zero_kernel<<<(NN / 4 + 255) / 256, 256>>>(d_cnt, NN / 4);
    count_kernel<<<(NE + 255) / 256, 256>>>(dst);

    // embed
    embed_kernel<<<(NN * DD + 255) / 256, 256>>>(node_features, embed_W, embed_b);

    for (int l = 0; l < LL; l++) {
        zero_kernel<<<(NN * HH / 4 + 255) / 256, 256>>>(d_agg, NN * HH / 4);
        msg_kernel<<<148, 256, MSG_SMEM>>>(edge_attr, src, dst,
                                           msg_W1 + l * EIN * HH, msg_b1 + l * HH,
                                           msg_W2 + l * HH * HH, msg_b2 + l * HH);
        upd_kernel<<<592, 128, UPD_SMEM>>>(upd_W + l * UIN * DD, upd_b + l * DD,
                                           ln_g + l * DD, ln_b + l * DD);
    }

    pred_kernel<<<296, 256, PRED_SMEM>>>(edge_attr, src, dst,
                                         pred_W1, pred_b1, pred_W2, pred_b2,
                                         pred_W3, pred_b3, out);
}

// round 2
// speedup vs baseline: 1.6462x; 1.6462x over previous
#include <cuda_runtime.h>
#include <math.h>

#define NN 50000
#define NE 500000
#define FN 7
#define FE 8
#define DD 64
#define HH 128
#define EIN 136          // 2*DD + FE
#define UIN 192          // DD + HH
#define LL 3
#define EPB 32           // edges per block-iteration (msg/pred)

typedef unsigned long long u64;

// packed fp32x2 fma (Blackwell): d = a*b + d elementwise on 2 floats
__device__ __forceinline__ void ffma2(u64 &d, u64 a, u64 b) {
    asm("fma.rn.f32x2 %0, %1, %2, %0;" : "+l"(d) : "l"(a), "l"(b));
}
__device__ __forceinline__ float f2sum(u64 a) {
    float lo, hi;
    asm("mov.b64 {%0, %1}, %2;" : "=f"(lo), "=f"(hi) : "l"(a));
    return lo + hi;
}
__device__ __forceinline__ void red_add_v4(float* p, float4 v) {
    u64 gp;
    asm("cvta.to.global.u64 %0, %1;" : "=l"(gp) : "l"(p));
    asm volatile("red.global.add.v4.f32 [%0], {%1, %2, %3, %4};"
                 :: "l"(gp), "f"(v.x), "f"(v.y), "f"(v.z), "f"(v.w) : "memory");
}

// ---------------- scratch ----------------
__device__ float g_x[NN * DD];
__device__ float g_agg[NN * HH];
__device__ float g_cnt[NN];

// ---------------- utility kernels ----------------
__global__ void zero_kernel(float* __restrict__ p, int n4) {
    int i = blockIdx.x * blockDim.x + threadIdx.x;
    if (i < n4) ((float4*)p)[i] = make_float4(0.f, 0.f, 0.f, 0.f);
}

__global__ void count_kernel(const int* __restrict__ dst) {
    int e = blockIdx.x * blockDim.x + threadIdx.x;
    if (e < NE) atomicAdd(&g_cnt[dst[e]], 1.0f);
}

__global__ void embed_kernel(const float* __restrict__ nf,
                             const float* __restrict__ W,
                             const float* __restrict__ b) {
    int idx = blockIdx.x * blockDim.x + threadIdx.x;  // over NN*DD
    if (idx >= NN * DD) return;
    int n = idx >> 6, d = idx & 63;
    float acc = b[d];
#pragma unroll
    for (int f = 0; f < FN; f++) acc += nf[n * FN + f] * W[f * DD + d];
    g_x[idx] = fmaxf(acc, 0.f);
}

// ---------------- fused edge message MLP + vectorized scatter ----------------
#define W1S 140   // padded transposed-row stride for W1^T (conflict-free LDS.128)
#define W2S 132   // padded transposed-row stride for W2^T
#define MSG_SMEM ((HH*W1S + HH*W2S + 2*HH + EPB*EIN + 2*EPB*HH) * 4)

__global__ void __launch_bounds__(512, 1)
msg_kernel(const float* __restrict__ ea,
           const int* __restrict__ src, const int* __restrict__ dst,
           const float* __restrict__ W1, const float* __restrict__ b1,
           const float* __restrict__ W2, const float* __restrict__ b2) {
    extern __shared__ float s[];
    float* sW1t = s;                   // [128][140]  W1^T
    float* sW2t = sW1t + HH * W1S;     // [128][132]  W2^T
    float* sB1  = sW2t + HH * W2S;
    float* sB2  = sB1 + HH;
    float* sIn  = sB2 + HH;            // [EPB][136]
    float* sH   = sIn + EPB * EIN;     // [EPB][128]
    float* sMsg = sH + EPB * HH;       // [EPB][128]

    const int tid = threadIdx.x;
    for (int i = tid; i < EIN * HH; i += 512) { int k = i >> 7, jj = i & 127; sW1t[jj * W1S + k] = W1[i]; }
    for (int i = tid; i < HH * HH; i += 512)  { int k = i >> 7, jj = i & 127; sW2t[jj * W2S + k] = W2[i]; }
    if (tid < HH) { sB1[tid] = b1[tid]; sB2[tid] = b2[tid]; }
    __syncthreads();

    const int j = tid & 127;           // output channel
    const int g = tid >> 7;            // edge group 0..3
    const int wid = tid >> 5, lane = tid & 31;
    const float b1v = sB1[j], b2v = sB2[j];

    for (int e0 = blockIdx.x * EPB; e0 < NE; e0 += gridDim.x * EPB) {
        // ---- stage [x[src] | x[dst] | ea] : warp -> 2 edges ----
#pragma unroll
        for (int t = 0; t < 2; t++) {
            int le = wid * 2 + t, ge = e0 + le;
            if (ge < NE) {
                int sN = src[ge], dN = dst[ge];
                float4 v = (lane < 16) ? ((const float4*)(g_x + sN * DD))[lane]
                                       : ((const float4*)(g_x + dN * DD))[lane - 16];
                ((float4*)(sIn + le * EIN))[lane] = v;
                if (lane < 2)
                    ((float4*)(sIn + le * EIN + 2 * DD))[lane] = ((const float4*)(ea + ge * FE))[lane];
            }
        }
        __syncthreads();

        // ---- GEMM1: h = relu(in @ W1 + b1), f32x2 k-pair packed ----
        {
            u64 acc[8];
#pragma unroll
            for (int c = 0; c < 8; c++) acc[c] = 0ull;
            const float* wr = sW1t + j * W1S;
#pragma unroll 2
            for (int k = 0; k < EIN; k += 4) {
                ulonglong2 w = *(const ulonglong2*)(wr + k);
#pragma unroll
                for (int c = 0; c < 8; c++) {
                    ulonglong2 v = *(const ulonglong2*)(sIn + (g + 4 * c) * EIN + k);
                    ffma2(acc[c], w.x, v.x);
                    ffma2(acc[c], w.y, v.y);
                }
            }
#pragma unroll
            for (int c = 0; c < 8; c++)
                sH[(g + 4 * c) * HH + j] = fmaxf(f2sum(acc[c]) + b1v, 0.f);
        }
        __syncthreads();

        // ---- GEMM2: msg = h @ W2 + b2 ----
        {
            u64 acc[8];
#pragma unroll
            for (int c = 0; c < 8; c++) acc[c] = 0ull;
            const float* wr = sW2t + j * W2S;
#pragma unroll 2
            for (int k = 0; k < HH; k += 4) {
                ulonglong2 w = *(const ulonglong2*)(wr + k);
#pragma unroll
                for (int c = 0; c < 8; c++) {
                    ulonglong2 v = *(const ulonglong2*)(sH + (g + 4 * c) * HH + k);
                    ffma2(acc[c], w.x, v.x);
                    ffma2(acc[c], w.y, v.y);
                }
            }
#pragma unroll
            for (int c = 0; c < 8; c++)
                sMsg[(g + 4 * c) * HH + j] = f2sum(acc[c]) + b2v;
        }
        __syncthreads();

        // ---- vectorized scatter: warp -> 2 edges, red.v4 per lane ----
#pragma unroll
        for (int t = 0; t < 2; t++) {
            int le = wid * 2 + t, ge = e0 + le;
            if (ge < NE) {
                int dN = dst[ge];
                float4 m = ((const float4*)(sMsg + le * HH))[lane];
                red_add_v4(g_agg + dN * HH + lane * 4, m);
            }
        }
        __syncthreads();
    }
}

// ---------------- node update + LayerNorm (shuffle reductions) ----------------
#define WUS 196
#define UPD_SMEM ((DD*WUS + 3*DD + 8*UIN + 32) * 4)

__global__ void __launch_bounds__(256, 2)
upd_kernel(const float* __restrict__ W, const float* __restrict__ b,
           const float* __restrict__ lg, const float* __restrict__ lb) {
    extern __shared__ float s[];
    float* sWt  = s;                   // [64][196]  W^T
    float* sB   = sWt + DD * WUS;
    float* sG   = sB + DD;
    float* sLB  = sG + DD;
    float* sNin = sLB + DD;            // [8][192]
    float* sRed = sNin + 8 * UIN;      // [8 nodes][2 warps][2 stats]

    const int tid = threadIdx.x;
    for (int i = tid; i < UIN * DD; i += 256) { int k = i >> 6, d = i & 63; sWt[d * WUS + k] = W[i]; }
    if (tid < DD) { sB[tid] = b[tid]; sG[tid] = lg[tid]; sLB[tid] = lb[tid]; }
    __syncthreads();

    const int d = tid & 63;
    const int g = tid >> 6;            // node group 0..3
    const int wg = (tid >> 5) & 1;     // warp within group
    const int wid = tid >> 5, lane = tid & 31;
    const float bv = sB[d], gv = sG[d], lbv = sLB[d];

    for (int n0 = blockIdx.x * 8; n0 < NN; n0 += gridDim.x * 8) {
        // stage: warp -> node
        {
            int n = n0 + wid;
            if (n < NN) {
                float inv = 1.f / (g_cnt[n] + 1e-6f);
                for (int i = lane; i < UIN; i += 32) {
                    float v = (i < DD) ? g_x[n * DD + i] : g_agg[n * HH + (i - DD)] * inv;
                    sNin[wid * UIN + i] = v;
                }
            }
        }
        __syncthreads();

        float outv[2];
        {
            u64 a0 = 0ull, a1 = 0ull;
            const float* wr = sWt + d * WUS;
            const float* in0 = sNin + g * UIN;
            const float* in1 = sNin + (g + 4) * UIN;
#pragma unroll 4
            for (int k = 0; k < UIN; k += 4) {
                ulonglong2 w = *(const ulonglong2*)(wr + k);
                ulonglong2 v0 = *(const ulonglong2*)(in0 + k);
                ulonglong2 v1 = *(const ulonglong2*)(in1 + k);
                ffma2(a0, w.x, v0.x); ffma2(a0, w.y, v0.y);
                ffma2(a1, w.x, v1.x); ffma2(a1, w.y, v1.y);
            }
            outv[0] = in0[d] + fmaxf(f2sum(a0) + bv, 0.f);
            outv[1] = in1[d] + fmaxf(f2sum(a1) + bv, 0.f);
        }
#pragma unroll
        for (int c = 0; c < 2; c++) {
            int ln = g + 4 * c;
            float s1 = outv[c], s2 = outv[c] * outv[c];
#pragma unroll
            for (int off = 16; off; off >>= 1) {
                s1 += __shfl_xor_sync(0xFFFFFFFFu, s1, off);
                s2 += __shfl_xor_sync(0xFFFFFFFFu, s2, off);
            }
            if (lane == 0) { sRed[(ln * 2 + wg) * 2] = s1; sRed[(ln * 2 + wg) * 2 + 1] = s2; }
        }
        __syncthreads();
#pragma unroll
        for (int c = 0; c < 2; c++) {
            int ln = g + 4 * c;
            int n = n0 + ln;
            if (n < NN) {
                float s1 = sRed[(ln * 2) * 2] + sRed[(ln * 2 + 1) * 2];
                float s2 = sRed[(ln * 2) * 2 + 1] + sRed[(ln * 2 + 1) * 2 + 1];
                float mu = s1 * (1.f / DD);
                float var = s2 * (1.f / DD) - mu * mu;
                g_x[n * DD + d] = (outv[c] - mu) * rsqrtf(var + 1e-5f) * gv + lbv;
            }
        }
        __syncthreads();
    }
}

// ---------------- edge predictor ----------------
#define PRED_SMEM ((HH*W1S + DD*W2S + DD + HH + DD + EPB*EIN + EPB*HH + EPB*DD) * 4)

__global__ void __launch_bounds__(512, 1)
pred_kernel(const float* __restrict__ ea,
            const int* __restrict__ src, const int* __restrict__ dst,
            const float* __restrict__ W1, const float* __restrict__ b1,
            const float* __restrict__ W2, const float* __restrict__ b2,
            const float* __restrict__ W3, const float* __restrict__ b3,
            float* __restrict__ out) {
    extern __shared__ float s[];
    float* sW1t = s;                   // [128][140]
    float* sW2t = sW1t + HH * W1S;     // [64][132]
    float* sW3  = sW2t + DD * W2S;     // 64
    float* sB1  = sW3 + DD;
    float* sB2  = sB1 + HH;
    float* sIn  = sB2 + DD;            // [EPB][136]
    float* sH1  = sIn + EPB * EIN;     // [EPB][128]
    float* sH2  = sH1 + EPB * HH;      // [EPB][64]

    const int tid = threadIdx.x;
    for (int i = tid; i < EIN * HH; i += 512) { int k = i >> 7, jj = i & 127; sW1t[jj * W1S + k] = W1[i]; }
    for (int i = tid; i < HH * DD; i += 512)  { int k = i >> 6, jj = i & 63;  sW2t[jj * W2S + k] = W2[i]; }
    if (tid < DD) sW3[tid] = W3[tid];
    if (tid < HH) sB1[tid] = b1[tid];
    if (tid < DD) sB2[tid] = b2[tid];
    __syncthreads();

    const int j  = tid & 127;
    const int g  = tid >> 7;           // 0..3
    const int j2 = tid & 63;
    const int g2 = tid >> 6;           // 0..7
    const int wid = tid >> 5, lane = tid & 31;
    const float b1v = sB1[j], b2v = sB2[j2], b3v = b3[0];

    for (int e0 = blockIdx.x * EPB; e0 < NE; e0 += gridDim.x * EPB) {
#pragma unroll
        for (int t = 0; t < 2; t++) {
            int le = wid * 2 + t, ge = e0 + le;
            if (ge < NE) {
                int sN = src[ge], dN = dst[ge];
                float4 v = (lane < 16) ? ((const float4*)(g_x + sN * DD))[lane]
                                       : ((const float4*)(g_x + dN * DD))[lane - 16];
                ((float4*)(sIn + le * EIN))[lane] = v;
                if (lane < 2)
                    ((float4*)(sIn + le * EIN + 2 * DD))[lane] = ((const float4*)(ea + ge * FE))[lane];
            }
        }
        __syncthreads();

        // GEMM1: 136 -> 128 relu
        {
            u64 acc[8];
#pragma unroll
            for (int c = 0; c < 8; c++) acc[c] = 0ull;
            const float* wr = sW1t + j * W1S;
#pragma unroll 2
            for (int k = 0; k < EIN; k += 4) {
                ulonglong2 w = *(const ulonglong2*)(wr + k);
#pragma unroll
                for (int c = 0; c < 8; c++) {
                    ulonglong2 v = *(const ulonglong2*)(sIn + (g + 4 * c) * EIN + k);
                    ffma2(acc[c], w.x, v.x);
                    ffma2(acc[c], w.y, v.y);
                }
            }
#pragma unroll
            for (int c = 0; c < 8; c++)
                sH1[(g + 4 * c) * HH + j] = fmaxf(f2sum(acc[c]) + b1v, 0.f);
        }
        __syncthreads();

        // GEMM2: 128 -> 64 relu
        {
            u64 acc[4];
#pragma unroll
            for (int c = 0; c < 4; c++) acc[c] = 0ull;
            const float* wr = sW2t + j2 * W2S;
#pragma unroll 2
            for (int k = 0; k < HH; k += 4) {
                ulonglong2 w = *(const ulonglong2*)(wr + k);
#pragma unroll
                for (int c = 0; c < 4; c++) {
                    ulonglong2 v = *(const ulonglong2*)(sH1 + (g2 + 8 * c) * HH + k);
                    ffma2(acc[c], w.x, v.x);
                    ffma2(acc[c], w.y, v.y);
                }
            }
#pragma unroll
            for (int c = 0; c < 4; c++)
                sH2[(g2 + 8 * c) * DD + j2] = fmaxf(f2sum(acc[c]) + b2v, 0.f);
        }
        __syncthreads();

        // final dot 64 -> 1 + tanh : warp -> 2 edges
#pragma unroll
        for (int t = 0; t < 2; t++) {
            int le = wid * 2 + t, ge = e0 + le;
            if (ge < NE) {
                float v = sH2[le * DD + lane] * sW3[lane]
                        + sH2[le * DD + 32 + lane] * sW3[32 + lane];
#pragma unroll
                for (int off = 16; off; off >>= 1) v += __shfl_xor_sync(0xFFFFFFFFu, v, off);
                if (lane == 0) out[ge] = tanhf(v + b3v);
            }
        }
        __syncthreads();
    }
}

// ---------------- launch ----------------
extern "C" void kernel_launch(void* const* d_in, const int* in_sizes, int n_in,
                              void* d_out, int out_size) {
    const float* node_features = (const float*)d_in[0];
    const float* edge_attr     = (const float*)d_in[1];
    const float* embed_W       = (const float*)d_in[2];
    const float* embed_b       = (const float*)d_in[3];
    const float* msg_W1        = (const float*)d_in[4];
    const float* msg_b1        = (const float*)d_in[5];
    const float* msg_W2        = (const float*)d_in[6];
    const float* msg_b2        = (const float*)d_in[7];
    const float* upd_W         = (const float*)d_in[8];
    const float* upd_b         = (const float*)d_in[9];
    const float* ln_g          = (const float*)d_in[10];
    const float* ln_b          = (const float*)d_in[11];
    const float* pred_W1       = (const float*)d_in[12];
    const float* pred_b1       = (const float*)d_in[13];
    const float* pred_W2       = (const float*)d_in[14];
    const float* pred_b2       = (const float*)d_in[15];
    const float* pred_W3       = (const float*)d_in[16];
    const float* pred_b3       = (const float*)d_in[17];
    const int*   edge_index    = (const int*)d_in[18];
    float* out = (float*)d_out;

    const int* src = edge_index;
    const int* dst = edge_index + NE;

    cudaFuncSetAttribute(msg_kernel,  cudaFuncAttributeMaxDynamicSharedMemorySize, MSG_SMEM);
    cudaFuncSetAttribute(pred_kernel, cudaFuncAttributeMaxDynamicSharedMemorySize, PRED_SMEM);
    cudaFuncSetAttribute(upd_kernel,  cudaFuncAttributeMaxDynamicSharedMemorySize, UPD_SMEM);

    float* d_agg; cudaGetSymbolAddress((void**)&d_agg, g_agg);
    float* d_cnt; cudaGetSymbolAddress((void**)&d_cnt, g_cnt);

    zero_kernel<<<(NN / 4 + 255) / 256, 256>>>(d_cnt, NN / 4);
    count_kernel<<<(NE + 255) / 256, 256>>>(dst);
    embed_kernel<<<(NN * DD + 255) / 256, 256>>>(node_features, embed_W, embed_b);

    for (int l = 0; l < LL; l++) {
        zero_kernel<<<(NN * HH / 4 + 255) / 256, 256>>>(d_agg, NN * HH / 4);
        msg_kernel<<<148, 512, MSG_SMEM>>>(edge_attr, src, dst,
                                           msg_W1 + l * EIN * HH, msg_b1 + l * HH,
                                           msg_W2 + l * HH * HH, msg_b2 + l * HH);
        upd_kernel<<<296, 256, UPD_SMEM>>>(upd_W + l * UIN * DD, upd_b + l * DD,
                                           ln_g + l * DD, ln_b + l * DD);
    }

    pred_kernel<<<148, 512, PRED_SMEM>>>(edge_attr, src, dst,
                                         pred_W1, pred_b1, pred_W2, pred_b2,
                                         pred_W3, pred_b3, out);
}

// round 3
// speedup vs baseline: 2.5000x; 1.5187x over previous
#include <cuda_runtime.h>
#include <math.h>

#define NN 50000
#define NE 500000
#define FN 7
#define FE 8
#define DD 64
#define HH 128
#define PP 256           // Pab width (src-part 128 | dst-part 128)
#define EIN 136          // 2*DD + FE (W1 row count)
#define UIN 192          // DD + HH
#define LL 3
#define EPB 32           // edges per block-iteration

typedef unsigned long long u64;

__device__ __forceinline__ void ffma2(u64 &d, u64 a, u64 b) {
    asm("fma.rn.f32x2 %0, %1, %2, %0;" : "+l"(d) : "l"(a), "l"(b));
}
__device__ __forceinline__ float f2sum(u64 a) {
    float lo, hi;
    asm("mov.b64 {%0, %1}, %2;" : "=f"(lo), "=f"(hi) : "l"(a));
    return lo + hi;
}
__device__ __forceinline__ void red_add_v4(float* p, float4 v) {
    u64 gp;
    asm("cvta.to.global.u64 %0, %1;" : "=l"(gp) : "l"(p));
    asm volatile("red.global.add.v4.f32 [%0], {%1, %2, %3, %4};"
                 :: "l"(gp), "f"(v.x), "f"(v.y), "f"(v.z), "f"(v.w) : "memory");
}

// ---------------- scratch ----------------
__device__ float g_x[NN * DD];
__device__ float g_agg[NN * HH];
__device__ float g_cnt[NN];
__device__ float g_pab[NN * PP];

// ---------------- init: zero agg + cnt ----------------
__global__ void init_kernel() {
    int i = blockIdx.x * blockDim.x + threadIdx.x;
    const int A4 = NN * HH / 4;
    if (i < A4) ((float4*)g_agg)[i] = make_float4(0.f, 0.f, 0.f, 0.f);
    else if (i < A4 + NN / 4) ((float4*)g_cnt)[i - A4] = make_float4(0.f, 0.f, 0.f, 0.f);
}

__global__ void count_kernel(const int* __restrict__ dst) {
    int e = blockIdx.x * blockDim.x + threadIdx.x;
    if (e < NE) atomicAdd(&g_cnt[dst[e]], 1.0f);
}

// ---------------- fused embed + node_lin(layer0) ----------------
#define NLS 68
#define EMB_SMEM ((PP*NLS + FN*DD + DD + 8*FN + 8*DD) * 4)

__global__ void __launch_bounds__(256, 2)
embed_nl_kernel(const float* __restrict__ nf,
                const float* __restrict__ eW, const float* __restrict__ eb,
                const float* __restrict__ W1) {
    extern __shared__ float s[];
    float* sWt = s;                    // [256][68]  combined W1[0:128] transposed
    float* sWe = sWt + PP * NLS;       // [7][64]
    float* sBe = sWe + FN * DD;        // [64]
    float* sNf = sBe + DD;             // [8][7]
    float* sX  = sNf + 8 * FN;         // [8][64]

    const int tid = threadIdx.x;
    for (int i = tid; i < DD * PP; i += 256) {
        int k = i >> 8, j = i & 255;
        sWt[j * NLS + k] = (j < HH) ? W1[k * HH + j] : W1[(DD + k) * HH + (j - HH)];
    }
    for (int i = tid; i < FN * DD; i += 256) sWe[i] = eW[i];
    if (tid < DD) sBe[tid] = eb[tid];
    __syncthreads();

    const int step = gridDim.x * 8;
    for (int n0 = blockIdx.x * 8; n0 < NN; n0 += step) {
        for (int i = tid; i < 8 * FN; i += 256) {
            int c = i / FN, f = i % FN;
            sNf[i] = nf[(n0 + c) * FN + f];
        }
        __syncthreads();
        // embed: 512 outputs over 256 threads
        for (int i = tid; i < 8 * DD; i += 256) {
            int c = i >> 6, d = i & 63;
            float xv = sBe[d];
#pragma unroll
            for (int f = 0; f < FN; f++) xv += sNf[c * FN + f] * sWe[f * DD + d];
            xv = fmaxf(xv, 0.f);
            sX[c * DD + d] = xv;
            g_x[(n0 + c) * DD + d] = xv;
        }
        __syncthreads();
        // Pab for layer 0
        u64 acc[8];
#pragma unroll
        for (int c = 0; c < 8; c++) acc[c] = 0ull;
        const float* wr = sWt + tid * NLS;
#pragma unroll 4
        for (int k = 0; k < DD; k += 4) {
            ulonglong2 w = *(const ulonglong2*)(wr + k);
#pragma unroll
            for (int c = 0; c < 8; c++) {
                ulonglong2 v = *(const ulonglong2*)(sX + c * DD + k);
                ffma2(acc[c], w.x, v.x);
                ffma2(acc[c], w.y, v.y);
            }
        }
#pragma unroll
        for (int c = 0; c < 8; c++)
            g_pab[(size_t)(n0 + c) * PP + tid] = f2sum(acc[c]);
        __syncthreads();
    }
}

// ---------------- node_lin: Pab = x @ W1[0:128] (per layer) ----------------
#define NL_SMEM ((PP*NLS + 8*DD) * 4)

__global__ void __launch_bounds__(256, 2)
node_lin_kernel(const float* __restrict__ W1) {
    extern __shared__ float s[];
    float* sWt = s;                    // [256][68]
    float* sX  = sWt + PP * NLS;       // [8][64]

    const int tid = threadIdx.x;
    for (int i = tid; i < DD * PP; i += 256) {
        int k = i >> 8, j = i & 255;
        sWt[j * NLS + k] = (j < HH) ? W1[k * HH + j] : W1[(DD + k) * HH + (j - HH)];
    }
    __syncthreads();

    const int step = gridDim.x * 8;
    for (int n0 = blockIdx.x * 8; n0 < NN; n0 += step) {
        for (int i = tid; i < 8 * DD; i += 256) {
            int c = i >> 6, k = i & 63;
            sX[i] = g_x[(n0 + c) * DD + k];
        }
        __syncthreads();
        u64 acc[8];
#pragma unroll
        for (int c = 0; c < 8; c++) acc[c] = 0ull;
        const float* wr = sWt + tid * NLS;
#pragma unroll 4
        for (int k = 0; k < DD; k += 4) {
            ulonglong2 w = *(const ulonglong2*)(wr + k);
#pragma unroll
            for (int c = 0; c < 8; c++) {
                ulonglong2 v = *(const ulonglong2*)(sX + c * DD + k);
                ffma2(acc[c], w.x, v.x);
                ffma2(acc[c], w.y, v.y);
            }
        }
#pragma unroll
        for (int c = 0; c < 8; c++)
            g_pab[(size_t)(n0 + c) * PP + tid] = f2sum(acc[c]);
        __syncthreads();
    }
}

// ---------------- fused edge message: phaseA(factored GEMM1) + GEMM2 + scatter ----------------
#define W2S 132
#define MSG_SMEM ((HH*W2S + 2*HH + 2*EPB*HH + 2*EPB*PP + 2*EPB*FE) * 4 + 2*EPB*4)

__global__ void __launch_bounds__(512, 1)
msg_kernel(const float* __restrict__ ea,
           const int* __restrict__ src, const int* __restrict__ dst,
           const float* __restrict__ W1, const float* __restrict__ b1,
           const float* __restrict__ W2, const float* __restrict__ b2) {
    extern __shared__ float s[];
    float* sW2t = s;                       // [128][132]
    float* sB1  = sW2t + HH * W2S;
    float* sB2  = sB1 + HH;
    float* sH   = sB2 + HH;                // [32][128]
    float* sMsg = sH + EPB * HH;           // [32][128]
    float* sPab = sMsg + EPB * HH;         // [2][32][256]
    float* sEa  = sPab + 2 * EPB * PP;     // [2][32][8]
    int*   sDst = (int*)(sEa + 2 * EPB * FE); // [2][32]

    const int tid = threadIdx.x;
    for (int i = tid; i < HH * HH; i += 512) { int k = i >> 7, j = i & 127; sW2t[j * W2S + k] = W2[i]; }
    if (tid < HH) { sB1[tid] = b1[tid]; sB2[tid] = b2[tid]; }
    __syncthreads();

    const int j = tid & 127, g = tid >> 7;
    const int wid = tid >> 5, lane = tid & 31;
    const int le0 = wid * 2;
    const float b1v = sB1[j], b2v = sB2[j];
    float w1c[8];
#pragma unroll
    for (int f = 0; f < 8; f++) w1c[f] = W1[(2 * DD + f) * HH + j];

    float4 pfa[2], pfb[2], pfe[2];
    int pd[2];

#define MSG_PREFETCH(BASE) { \
    _Pragma("unroll") \
    for (int t = 0; t < 2; t++) { \
        int ge = (BASE) + le0 + t; \
        int sN = src[ge], dN = dst[ge]; \
        pd[t] = dN; \
        pfa[t] = ((const float4*)(g_pab + (size_t)sN * PP))[lane]; \
        pfb[t] = ((const float4*)(g_pab + (size_t)dN * PP + HH))[lane]; \
        if (lane < 2) pfe[t] = ((const float4*)(ea + (size_t)ge * FE))[lane]; } }

#define MSG_STORE(B) { \
    _Pragma("unroll") \
    for (int t = 0; t < 2; t++) { \
        int le = le0 + t; \
        ((float4*)(sPab + (B) * EPB * PP + le * PP))[lane] = pfa[t]; \
        ((float4*)(sPab + (B) * EPB * PP + le * PP + HH))[lane] = pfb[t]; \
        if (lane < 2) ((float4*)(sEa + (B) * EPB * FE + le * FE))[lane] = pfe[t]; \
        if (lane == 0) sDst[(B) * EPB + le] = pd[t]; } }

    int e0 = blockIdx.x * EPB;
    const int step = gridDim.x * EPB;
    int buf = 0;
    if (e0 < NE) { MSG_PREFETCH(e0); MSG_STORE(0); }

    for (; e0 < NE; e0 += step) {
        int enext = e0 + step;
        __syncthreads();                         // staged buf visible; sH free
        if (enext < NE) MSG_PREFETCH(enext);     // LDGs overlap phaseA+GEMM2

        // phase A: h = relu(Pa[src] + Pb[dst] + ea@W1c + b1)
        const float* pabB = sPab + buf * EPB * PP;
        const float* eaB  = sEa + buf * EPB * FE;
#pragma unroll
        for (int c = 0; c < 8; c++) {
            int e = g + 4 * c;
            float hv = pabB[e * PP + j] + pabB[e * PP + HH + j] + b1v;
            float4 a0 = ((const float4*)(eaB + e * FE))[0];
            float4 a1 = ((const float4*)(eaB + e * FE))[1];
            hv = fmaf(a0.x, w1c[0], hv); hv = fmaf(a0.y, w1c[1], hv);
            hv = fmaf(a0.z, w1c[2], hv); hv = fmaf(a0.w, w1c[3], hv);
            hv = fmaf(a1.x, w1c[4], hv); hv = fmaf(a1.y, w1c[5], hv);
            hv = fmaf(a1.z, w1c[6], hv); hv = fmaf(a1.w, w1c[7], hv);
            sH[e * HH + j] = fmaxf(hv, 0.f);
        }
        __syncthreads();                         // sH visible

        // GEMM2: msg = h @ W2 + b2
        u64 acc[8];
#pragma unroll
        for (int c = 0; c < 8; c++) acc[c] = 0ull;
        const float* wr = sW2t + j * W2S;
#pragma unroll 2
        for (int k = 0; k < HH; k += 4) {
            ulonglong2 w = *(const ulonglong2*)(wr + k);
#pragma unroll
            for (int c = 0; c < 8; c++) {
                ulonglong2 v = *(const ulonglong2*)(sH + (g + 4 * c) * HH + k);
                ffma2(acc[c], w.x, v.x);
                ffma2(acc[c], w.y, v.y);
            }
        }
#pragma unroll
        for (int c = 0; c < 8; c++)
            sMsg[(g + 4 * c) * HH + j] = f2sum(acc[c]) + b2v;

        if (enext < NE) MSG_STORE(buf ^ 1);
        __syncthreads();                         // sMsg visible

        // vectorized scatter
#pragma unroll
        for (int t = 0; t < 2; t++) {
            int le = le0 + t;
            int dN = sDst[buf * EPB + le];
            float4 m = ((const float4*)(sMsg + le * HH))[lane];
            red_add_v4(g_agg + (size_t)dN * HH + lane * 4, m);
        }
        buf ^= 1;
    }
#undef MSG_PREFETCH
#undef MSG_STORE
}

// ---------------- node update + LayerNorm + fused agg-zero ----------------
#define WUS 196
#define UPD_SMEM ((DD*WUS + 3*DD + 8*UIN + 32) * 4)

__global__ void __launch_bounds__(256, 2)
upd_kernel(const float* __restrict__ W, const float* __restrict__ b,
           const float* __restrict__ lg, const float* __restrict__ lb) {
    extern __shared__ float s[];
    float* sWt  = s;                   // [64][196]
    float* sB   = sWt + DD * WUS;
    float* sG   = sB + DD;
    float* sLB  = sG + DD;
    float* sNin = sLB + DD;            // [8][192]
    float* sRed = sNin + 8 * UIN;

    const int tid = threadIdx.x;
    for (int i = tid; i < UIN * DD; i += 256) { int k = i >> 6, d = i & 63; sWt[d * WUS + k] = W[i]; }
    if (tid < DD) { sB[tid] = b[tid]; sG[tid] = lg[tid]; sLB[tid] = lb[tid]; }
    __syncthreads();

    const int d = tid & 63;
    const int g = tid >> 6;
    const int wg = (tid >> 5) & 1;
    const int wid = tid >> 5, lane = tid & 31;
    const float bv = sB[d], gv = sG[d], lbv = sLB[d];

    for (int n0 = blockIdx.x * 8; n0 < NN; n0 += gridDim.x * 8) {
        {
            int n = n0 + wid;
            if (n < NN) {
                float inv = 1.f / (g_cnt[n] + 1e-6f);
                for (int i = lane; i < UIN; i += 32) {
                    float v = (i < DD) ? g_x[n * DD + i] : g_agg[n * HH + (i - DD)] * inv;
                    sNin[wid * UIN + i] = v;
                }
            }
        }
        __syncthreads();
        // zero this node's agg row for the next layer (reads are complete)
        {
            int n = n0 + wid;
            if (n < NN) ((float4*)(g_agg + (size_t)n * HH))[lane] = make_float4(0.f, 0.f, 0.f, 0.f);
        }

        float outv[2];
        {
            u64 a0 = 0ull, a1 = 0ull;
            const float* wr = sWt + d * WUS;
            const float* in0 = sNin + g * UIN;
            const float* in1 = sNin + (g + 4) * UIN;
#pragma unroll 4
            for (int k = 0; k < UIN; k += 4) {
                ulonglong2 w = *(const ulonglong2*)(wr + k);
                ulonglong2 v0 = *(const ulonglong2*)(in0 + k);
                ulonglong2 v1 = *(const ulonglong2*)(in1 + k);
                ffma2(a0, w.x, v0.x); ffma2(a0, w.y, v0.y);
                ffma2(a1, w.x, v1.x); ffma2(a1, w.y, v1.y);
            }
            outv[0] = in0[d] + fmaxf(f2sum(a0) + bv, 0.f);
            outv[1] = in1[d] + fmaxf(f2sum(a1) + bv, 0.f);
        }
#pragma unroll
        for (int c = 0; c < 2; c++) {
            int ln = g + 4 * c;
            float s1 = outv[c], s2 = outv[c] * outv[c];
#pragma unroll
            for (int off = 16; off; off >>= 1) {
                s1 += __shfl_xor_sync(0xFFFFFFFFu, s1, off);
                s2 += __shfl_xor_sync(0xFFFFFFFFu, s2, off);
            }
            if (lane == 0) { sRed[(ln * 2 + wg) * 2] = s1; sRed[(ln * 2 + wg) * 2 + 1] = s2; }
        }
        __syncthreads();
#pragma unroll
        for (int c = 0; c < 2; c++) {
            int ln = g + 4 * c;
            int n = n0 + ln;
            if (n < NN) {
                float s1 = sRed[(ln * 2) * 2] + sRed[(ln * 2 + 1) * 2];
                float s2 = sRed[(ln * 2) * 2 + 1] + sRed[(ln * 2 + 1) * 2 + 1];
                float mu = s1 * (1.f / DD);
                float var = s2 * (1.f / DD) - mu * mu;
                g_x[n * DD + d] = (outv[c] - mu) * rsqrtf(var + 1e-5f) * gv + lbv;
            }
        }
        __syncthreads();
    }
}

// ---------------- edge predictor (factored first layer) ----------------
#define PRED_SMEM ((DD*W2S + DD + HH + DD + EPB*HH + EPB*DD + 2*EPB*PP + 2*EPB*FE) * 4)

__global__ void __launch_bounds__(512, 1)
pred_kernel(const float* __restrict__ ea,
            const int* __restrict__ src, const int* __restrict__ dst,
            const float* __restrict__ W1, const float* __restrict__ b1,
            const float* __restrict__ W2, const float* __restrict__ b2,
            const float* __restrict__ W3, const float* __restrict__ b3,
            float* __restrict__ out) {
    extern __shared__ float s[];
    float* sW2t = s;                   // [64][132]
    float* sW3  = sW2t + DD * W2S;     // [64]
    float* sB1  = sW3 + DD;            // [128]
    float* sB2  = sB1 + HH;            // [64]
    float* sH1  = sB2 + DD;            // [32][128]
    float* sH2  = sH1 + EPB * HH;      // [32][64]
    float* sPab = sH2 + EPB * DD;      // [2][32][256]
    float* sEa  = sPab + 2 * EPB * PP; // [2][32][8]

    const int tid = threadIdx.x;
    for (int i = tid; i < HH * DD; i += 512) { int k = i >> 6, jj = i & 63; sW2t[jj * W2S + k] = W2[i]; }
    if (tid < DD) sW3[tid] = W3[tid];
    if (tid < HH) sB1[tid] = b1[tid];
    if (tid < DD) sB2[tid] = b2[tid];
    __syncthreads();

    const int j = tid & 127, g = tid >> 7;
    const int j2 = tid & 63, g2 = tid >> 6;
    const int wid = tid >> 5, lane = tid & 31;
    const int le0 = wid * 2;
    const float b1v = sB1[j], b2v = sB2[j2], b3v = b3[0];
    float w1c[8];
#pragma unroll
    for (int f = 0; f < 8; f++) w1c[f] = W1[(2 * DD + f) * HH + j];

    float4 pfa[2], pfb[2], pfe[2];

#define PRD_PREFETCH(BASE) { \
    _Pragma("unroll") \
    for (int t = 0; t < 2; t++) { \
        int ge = (BASE) + le0 + t; \
        int sN = src[ge], dN = dst[ge]; \
        pfa[t] = ((const float4*)(g_pab + (size_t)sN * PP))[lane]; \
        pfb[t] = ((const float4*)(g_pab + (size_t)dN * PP + HH))[lane]; \
        if (lane < 2) pfe[t] = ((const float4*)(ea + (size_t)ge * FE))[lane]; } }

#define PRD_STORE(B) { \
    _Pragma("unroll") \
    for (int t = 0; t < 2; t++) { \
        int le = le0 + t; \
        ((float4*)(sPab + (B) * EPB * PP + le * PP))[lane] = pfa[t]; \
        ((float4*)(sPab + (B) * EPB * PP + le * PP + HH))[lane] = pfb[t]; \
        if (lane < 2) ((float4*)(sEa + (B) * EPB * FE + le * FE))[lane] = pfe[t]; } }

    int e0 = blockIdx.x * EPB;
    const int step = gridDim.x * EPB;
    int buf = 0;
    if (e0 < NE) { PRD_PREFETCH(e0); PRD_STORE(0); }

    for (; e0 < NE; e0 += step) {
        int enext = e0 + step;
        __syncthreads();
        if (enext < NE) PRD_PREFETCH(enext);

        // phase A: h1 = relu(Pa[src] + Pb[dst] + ea@W1c + b1)
        const float* pabB = sPab + buf * EPB * PP;
        const float* eaB  = sEa + buf * EPB * FE;
#pragma unroll
        for (int c = 0; c < 8; c++) {
            int e = g + 4 * c;
            float hv = pabB[e * PP + j] + pabB[e * PP + HH + j] + b1v;
            float4 a0 = ((const float4*)(eaB + e * FE))[0];
            float4 a1 = ((const float4*)(eaB + e * FE))[1];
            hv = fmaf(a0.x, w1c[0], hv); hv = fmaf(a0.y, w1c[1], hv);
            hv = fmaf(a0.z, w1c[2], hv); hv = fmaf(a0.w, w1c[3], hv);
            hv = fmaf(a1.x, w1c[4], hv); hv = fmaf(a1.y, w1c[5], hv);
            hv = fmaf(a1.z, w1c[6], hv); hv = fmaf(a1.w, w1c[7], hv);
            sH1[e * HH + j] = fmaxf(hv, 0.f);
        }
        __syncthreads();

        // GEMM2: h2 = relu(h1 @ W2 + b2), 128->64
        u64 acc[4];
#pragma unroll
        for (int c = 0; c < 4; c++) acc[c] = 0ull;
        const float* wr = sW2t + j2 * W2S;
#pragma unroll 2
        for (int k = 0; k < HH; k += 4) {
            ulonglong2 w = *(const ulonglong2*)(wr + k);
#pragma unroll
            for (int c = 0; c < 4; c++) {
                ulonglong2 v = *(const ulonglong2*)(sH1 + (g2 + 8 * c) * HH + k);
                ffma2(acc[c], w.x, v.x);
                ffma2(acc[c], w.y, v.y);
            }
        }
#pragma unroll
        for (int c = 0; c < 4; c++)
            sH2[(g2 + 8 * c) * DD + j2] = fmaxf(f2sum(acc[c]) + b2v, 0.f);

        if (enext < NE) PRD_STORE(buf ^ 1);
        __syncthreads();

        // final dot 64 -> 1 + tanh : warp -> its 2 staged edges
#pragma unroll
        for (int t = 0; t < 2; t++) {
            int le = le0 + t, ge = e0 + le;
            float v = sH2[le * DD + lane] * sW3[lane]
                    + sH2[le * DD + 32 + lane] * sW3[32 + lane];
#pragma unroll
            for (int off = 16; off; off >>= 1) v += __shfl_xor_sync(0xFFFFFFFFu, v, off);
            if (lane == 0) out[ge] = tanhf(v + b3v);
        }
        buf ^= 1;
    }
#undef PRD_PREFETCH
#undef PRD_STORE
}

// ---------------- launch ----------------
extern "C" void kernel_launch(void* const* d_in, const int* in_sizes, int n_in,
                              void* d_out, int out_size) {
    const float* node_features = (const float*)d_in[0];
    const float* edge_attr     = (const float*)d_in[1];
    const float* embed_W       = (const float*)d_in[2];
    const float* embed_b       = (const float*)d_in[3];
    const float* msg_W1        = (const float*)d_in[4];
    const float* msg_b1        = (const float*)d_in[5];
    const float* msg_W2        = (const float*)d_in[6];
    const float* msg_b2        = (const float*)d_in[7];
    const float* upd_W         = (const float*)d_in[8];
    const float* upd_b         = (const float*)d_in[9];
    const float* ln_g          = (const float*)d_in[10];
    const float* ln_b          = (const float*)d_in[11];
    const float* pred_W1       = (const float*)d_in[12];
    const float* pred_b1       = (const float*)d_in[13];
    const float* pred_W2       = (const float*)d_in[14];
    const float* pred_b2       = (const float*)d_in[15];
    const float* pred_W3       = (const float*)d_in[16];
    const float* pred_b3       = (const float*)d_in[17];
    const int*   edge_index    = (const int*)d_in[18];
    float* out = (float*)d_out;

    const int* src = edge_index;
    const int* dst = edge_index + NE;

    cudaFuncSetAttribute(msg_kernel,     cudaFuncAttributeMaxDynamicSharedMemorySize, MSG_SMEM);
    cudaFuncSetAttribute(pred_kernel,    cudaFuncAttributeMaxDynamicSharedMemorySize, PRED_SMEM);
    cudaFuncSetAttribute(upd_kernel,     cudaFuncAttributeMaxDynamicSharedMemorySize, UPD_SMEM);
    cudaFuncSetAttribute(node_lin_kernel, cudaFuncAttributeMaxDynamicSharedMemorySize, NL_SMEM);
    cudaFuncSetAttribute(embed_nl_kernel, cudaFuncAttributeMaxDynamicSharedMemorySize, EMB_SMEM);

    // 0: init (zero agg + cnt)
    init_kernel<<<(NN * HH / 4 + NN / 4 + 255) / 256, 256>>>();
    // 1: counts
    count_kernel<<<(NE + 255) / 256, 256>>>(dst);
    // 2: embed + Pab(layer0)
    embed_nl_kernel<<<296, 256, EMB_SMEM>>>(node_features, embed_W, embed_b, msg_W1);

    for (int l = 0; l < LL; l++) {
        // 3 (l=0): msg — ncu-profiled launch
        msg_kernel<<<148, 512, MSG_SMEM>>>(edge_attr, src, dst,
                                           msg_W1 + l * EIN * HH, msg_b1 + l * HH,
                                           msg_W2 + l * HH * HH, msg_b2 + l * HH);
        upd_kernel<<<296, 256, UPD_SMEM>>>(upd_W + l * UIN * DD, upd_b + l * DD,
                                           ln_g + l * DD, ln_b + l * DD);
        const float* nextW1 = (l < LL - 1) ? (msg_W1 + (l + 1) * EIN * HH) : pred_W1;
        node_lin_kernel<<<296, 256, NL_SMEM>>>(nextW1);
    }

    pred_kernel<<<148, 512, PRED_SMEM>>>(edge_attr, src, dst,
                                         pred_W1, pred_b1, pred_W2, pred_b2,
                                         pred_W3, pred_b3, out);
}

// round 5
// speedup vs baseline: 3.0167x; 1.2067x over previous
#include <cuda_runtime.h>
#include <math.h>

#define NN 50000
#define NE 500000
#define FN 7
#define FE 8
#define DD 64
#define HH 128
#define PP 256           // Pab width (src-part 128 | dst-part 128)
#define EIN 136
#define UIN 192
#define LL 3
#define EPB 64           // edges per block-iteration (msg/pred)

typedef unsigned long long u64;

__device__ __forceinline__ void ffma2(u64 &d, u64 a, u64 b) {
    asm("fma.rn.f32x2 %0, %1, %2, %0;" : "+l"(d) : "l"(a), "l"(b));
}
__device__ __forceinline__ float f2sum(u64 a) {
    float lo, hi;
    asm("mov.b64 {%0, %1}, %2;" : "=f"(lo), "=f"(hi) : "l"(a));
    return lo + hi;
}
__device__ __forceinline__ void red_add_v4(float* p, float4 v) {
    u64 gp;
    asm("cvta.to.global.u64 %0, %1;" : "=l"(gp) : "l"(p));
    asm volatile("red.global.add.v4.f32 [%0], {%1, %2, %3, %4};"
                 :: "l"(gp), "f"(v.x), "f"(v.y), "f"(v.z), "f"(v.w) : "memory");
}

// ---------------- scratch ----------------
__device__ float g_x[NN * DD];
__device__ float g_agg[NN * HH];
__device__ float g_cnt[NN];
__device__ float g_pab[NN * PP];

// ---------------- init ----------------
__global__ void init_kernel() {
    int i = blockIdx.x * blockDim.x + threadIdx.x;
    const int A4 = NN * HH / 4;
    if (i < A4) ((float4*)g_agg)[i] = make_float4(0.f, 0.f, 0.f, 0.f);
    else if (i < A4 + NN / 4) ((float4*)g_cnt)[i - A4] = make_float4(0.f, 0.f, 0.f, 0.f);
}

__global__ void count_kernel(const int* __restrict__ dst) {
    int e = blockIdx.x * blockDim.x + threadIdx.x;
    if (e < NE) atomicAdd(&g_cnt[dst[e]], 1.0f);
}

// ---------------- fused embed + node_lin(layer0) ----------------
#define NLS 68
#define EMB_SMEM ((PP*NLS + FN*DD + DD + 8*FN + 8*DD) * 4)

__global__ void __launch_bounds__(256, 2)
embed_nl_kernel(const float* __restrict__ nf,
                const float* __restrict__ eW, const float* __restrict__ eb,
                const float* __restrict__ W1) {
    extern __shared__ float s[];
    float* sWt = s;                    // [256][68]
    float* sWe = sWt + PP * NLS;
    float* sBe = sWe + FN * DD;
    float* sNf = sBe + DD;
    float* sX  = sNf + 8 * FN;

    const int tid = threadIdx.x;
    for (int i = tid; i < DD * PP; i += 256) {
        int k = i >> 8, j = i & 255;
        sWt[j * NLS + k] = (j < HH) ? W1[k * HH + j] : W1[(DD + k) * HH + (j - HH)];
    }
    for (int i = tid; i < FN * DD; i += 256) sWe[i] = eW[i];
    if (tid < DD) sBe[tid] = eb[tid];
    __syncthreads();

    const int step = gridDim.x * 8;
    for (int n0 = blockIdx.x * 8; n0 < NN; n0 += step) {
        for (int i = tid; i < 8 * FN; i += 256) {
            int c = i / FN, f = i % FN;
            sNf[i] = nf[(n0 + c) * FN + f];
        }
        __syncthreads();
        for (int i = tid; i < 8 * DD; i += 256) {
            int c = i >> 6, d = i & 63;
            float xv = sBe[d];
#pragma unroll
            for (int f = 0; f < FN; f++) xv += sNf[c * FN + f] * sWe[f * DD + d];
            xv = fmaxf(xv, 0.f);
            sX[c * DD + d] = xv;
            g_x[(n0 + c) * DD + d] = xv;
        }
        __syncthreads();
        u64 acc[8];
#pragma unroll
        for (int c = 0; c < 8; c++) acc[c] = 0ull;
        const float* wr = sWt + tid * NLS;
#pragma unroll 4
        for (int k = 0; k < DD; k += 4) {
            ulonglong2 w = *(const ulonglong2*)(wr + k);
#pragma unroll
            for (int c = 0; c < 8; c++) {
                ulonglong2 v = *(const ulonglong2*)(sX + c * DD + k);
                ffma2(acc[c], w.x, v.x);
                ffma2(acc[c], w.y, v.y);
            }
        }
#pragma unroll
        for (int c = 0; c < 8; c++)
            g_pab[(size_t)(n0 + c) * PP + tid] = f2sum(acc[c]);
        __syncthreads();
    }
}

// ---------------- node_lin ----------------
#define NL_SMEM ((PP*NLS + 8*DD) * 4)

__global__ void __launch_bounds__(256, 2)
node_lin_kernel(const float* __restrict__ W1) {
    extern __shared__ float s[];
    float* sWt = s;
    float* sX  = sWt + PP * NLS;

    const int tid = threadIdx.x;
    for (int i = tid; i < DD * PP; i += 256) {
        int k = i >> 8, j = i & 255;
        sWt[j * NLS + k] = (j < HH) ? W1[k * HH + j] : W1[(DD + k) * HH + (j - HH)];
    }
    __syncthreads();

    const int step = gridDim.x * 8;
    for (int n0 = blockIdx.x * 8; n0 < NN; n0 += step) {
        for (int i = tid; i < 8 * DD; i += 256) {
            int c = i >> 6, k = i & 63;
            sX[i] = g_x[(n0 + c) * DD + k];
        }
        __syncthreads();
        u64 acc[8];
#pragma unroll
        for (int c = 0; c < 8; c++) acc[c] = 0ull;
        const float* wr = sWt + tid * NLS;
#pragma unroll 4
        for (int k = 0; k < DD; k += 4) {
            ulonglong2 w = *(const ulonglong2*)(wr + k);
#pragma unroll
            for (int c = 0; c < 8; c++) {
                ulonglong2 v = *(const ulonglong2*)(sX + c * DD + k);
                ffma2(acc[c], w.x, v.x);
                ffma2(acc[c], w.y, v.y);
            }
        }
#pragma unroll
        for (int c = 0; c < 8; c++)
            g_pab[(size_t)(n0 + c) * PP + tid] = f2sum(acc[c]);
        __syncthreads();
    }
}

// ---------------- fused edge message (EPB=64, E8C2 GEMM2, tail-guarded) ----------------
#define W2S 132
#define MSG_SMEM ((HH*W2S + 2*HH + EPB*HH + EPB*HH + EPB*PP + EPB*FE) * 4)

__global__ void __launch_bounds__(512, 1)
msg_kernel(const float* __restrict__ ea,
           const int* __restrict__ src, const int* __restrict__ dst,
           const float* __restrict__ W1, const float* __restrict__ b1,
           const float* __restrict__ W2, const float* __restrict__ b2) {
    extern __shared__ float s[];
    float* sW2t = s;                       // [128][132]
    float* sB1  = sW2t + HH * W2S;
    float* sB2  = sB1 + HH;
    float* sH   = sB2 + HH;                // [64][128]
    float* sMsg = sH + EPB * HH;           // [64][128]
    float* sPab = sMsg + EPB * HH;         // [64][256]
    float* sEa  = sPab + EPB * PP;         // [64][8]

    const int tid = threadIdx.x;
    for (int i = tid; i < HH * HH; i += 512) { int k = i >> 7, j = i & 127; sW2t[j * W2S + k] = W2[i]; }
    if (tid < HH) { sB1[tid] = b1[tid]; sB2[tid] = b2[tid]; }

    const int j = tid & 127, g = tid >> 7;       // phaseA mapping
    const int j2 = tid & 63, eg = tid >> 6;      // GEMM2: 8 edge-groups of 8, 2 ch
    const int wid = tid >> 5, lane = tid & 31;
    const float b1v = b1[j];
    const float b2lo = b2[j2], b2hi = b2[j2 + 64];
    float w1c[8];
#pragma unroll
    for (int f = 0; f < 8; f++) w1c[f] = W1[(2 * DD + f) * HH + j];

    // staging: each warp owns 4 edges (wid*4 + t)
    float4 pfa[4], pfb[4];
    float pfe;
    int pd[4], pd_cur[4];                        // dst node or -1 if invalid
    const int sl_t = lane >> 3, sl_f = lane & 7;

#define MSG_PREFETCH(BASE) { \
    _Pragma("unroll") \
    for (int t = 0; t < 4; t++) { \
        int ge = (BASE) + wid * 4 + t; \
        bool ok = ge < NE; \
        int gc = ok ? ge : NE - 1; \
        int sN = src[gc], dN = dst[gc]; \
        pd[t] = ok ? dN : -1; \
        pfa[t] = ((const float4*)(g_pab + (size_t)sN * PP))[lane]; \
        pfb[t] = ((const float4*)(g_pab + (size_t)dN * PP + HH))[lane]; } \
    { int ge = (BASE) + wid * 4 + sl_t; \
      int gc = (ge < NE) ? ge : NE - 1; \
      pfe = ea[(size_t)gc * FE + sl_f]; } }

#define MSG_STORE() { \
    _Pragma("unroll") \
    for (int t = 0; t < 4; t++) { \
        int le = wid * 4 + t; \
        ((float4*)(sPab + le * PP))[lane] = pfa[t]; \
        ((float4*)(sPab + le * PP + HH))[lane] = pfb[t]; } \
    sEa[(wid * 4 + sl_t) * FE + sl_f] = pfe; }

    int e0 = blockIdx.x * EPB;
    const int step = gridDim.x * EPB;
    if (e0 < NE) { MSG_PREFETCH(e0); MSG_STORE(); }

    for (; e0 < NE; e0 += step) {
        int enext = e0 + step;
        __syncthreads();                         // staging visible

        // ---- phase A: h = relu(Pa + Pb + ea@W1c + b1) ----
#pragma unroll
        for (int c = 0; c < 16; c++) {
            int e = g + 4 * c;
            float hv = sPab[e * PP + j] + sPab[e * PP + HH + j] + b1v;
            float4 a0 = ((const float4*)(sEa + e * FE))[0];
            float4 a1 = ((const float4*)(sEa + e * FE))[1];
            hv = fmaf(a0.x, w1c[0], hv); hv = fmaf(a0.y, w1c[1], hv);
            hv = fmaf(a0.z, w1c[2], hv); hv = fmaf(a0.w, w1c[3], hv);
            hv = fmaf(a1.x, w1c[4], hv); hv = fmaf(a1.y, w1c[5], hv);
            hv = fmaf(a1.z, w1c[6], hv); hv = fmaf(a1.w, w1c[7], hv);
            sH[e * HH + j] = fmaxf(hv, 0.f);
        }
        // prefetch next (LDGs overlap GEMM2)
#pragma unroll
        for (int t = 0; t < 4; t++) pd_cur[t] = pd[t];
        if (enext < NE) MSG_PREFETCH(enext);
        __syncthreads();                         // sH visible, sPab reads done

        // ---- GEMM2: E=8 edges x C=2 channels per thread ----
        u64 aLo[8], aHi[8];
#pragma unroll
        for (int c = 0; c < 8; c++) { aLo[c] = 0ull; aHi[c] = 0ull; }
        const float* wr0 = sW2t + j2 * W2S;
        const float* wr1 = sW2t + (j2 + 64) * W2S;
#pragma unroll 2
        for (int k = 0; k < HH; k += 4) {
            ulonglong2 w0 = *(const ulonglong2*)(wr0 + k);
            ulonglong2 w1 = *(const ulonglong2*)(wr1 + k);
#pragma unroll
            for (int c = 0; c < 8; c++) {
                ulonglong2 v = *(const ulonglong2*)(sH + (eg * 8 + c) * HH + k);
                ffma2(aLo[c], w0.x, v.x);
                ffma2(aLo[c], w0.y, v.y);
                ffma2(aHi[c], w1.x, v.x);
                ffma2(aHi[c], w1.y, v.y);
            }
        }
#pragma unroll
        for (int c = 0; c < 8; c++) {
            int e = eg * 8 + c;
            sMsg[e * HH + j2]      = f2sum(aLo[c]) + b2lo;
            sMsg[e * HH + 64 + j2] = f2sum(aHi[c]) + b2hi;
        }
        __syncthreads();                         // sMsg visible

        // ---- scatter: warp -> its 4 staged edges (skip invalid) ----
#pragma unroll
        for (int t = 0; t < 4; t++) {
            int le = wid * 4 + t;
            if (pd_cur[t] >= 0) {
                float4 m = ((const float4*)(sMsg + le * HH))[lane];
                red_add_v4(g_agg + (size_t)pd_cur[t] * HH + lane * 4, m);
            }
        }
        // store next staging (LDG data arrived during GEMM2)
        if (enext < NE) MSG_STORE();
    }
#undef MSG_PREFETCH
#undef MSG_STORE
}

// ---------------- node update + LayerNorm + fused agg-zero ----------------
#define WUS 196
#define UPD_SMEM ((DD*WUS + 3*DD + 8*UIN + 32) * 4)

__global__ void __launch_bounds__(256, 2)
upd_kernel(const float* __restrict__ W, const float* __restrict__ b,
           const float* __restrict__ lg, const float* __restrict__ lb) {
    extern __shared__ float s[];
    float* sWt  = s;
    float* sB   = sWt + DD * WUS;
    float* sG   = sB + DD;
    float* sLB  = sG + DD;
    float* sNin = sLB + DD;
    float* sRed = sNin + 8 * UIN;

    const int tid = threadIdx.x;
    for (int i = tid; i < UIN * DD; i += 256) { int k = i >> 6, d = i & 63; sWt[d * WUS + k] = W[i]; }
    if (tid < DD) { sB[tid] = b[tid]; sG[tid] = lg[tid]; sLB[tid] = lb[tid]; }
    __syncthreads();

    const int d = tid & 63;
    const int g = tid >> 6;
    const int wg = (tid >> 5) & 1;
    const int wid = tid >> 5, lane = tid & 31;
    const float bv = sB[d], gv = sG[d], lbv = sLB[d];

    for (int n0 = blockIdx.x * 8; n0 < NN; n0 += gridDim.x * 8) {
        {
            int n = n0 + wid;
            if (n < NN) {
                float inv = 1.f / (g_cnt[n] + 1e-6f);
                for (int i = lane; i < UIN; i += 32) {
                    float v = (i < DD) ? g_x[n * DD + i] : g_agg[n * HH + (i - DD)] * inv;
                    sNin[wid * UIN + i] = v;
                }
            }
        }
        __syncthreads();
        {
            int n = n0 + wid;
            if (n < NN) ((float4*)(g_agg + (size_t)n * HH))[lane] = make_float4(0.f, 0.f, 0.f, 0.f);
        }

        float outv[2];
        {
            u64 a0 = 0ull, a1 = 0ull;
            const float* wr = sWt + d * WUS;
            const float* in0 = sNin + g * UIN;
            const float* in1 = sNin + (g + 4) * UIN;
#pragma unroll 4
            for (int k = 0; k < UIN; k += 4) {
                ulonglong2 w = *(const ulonglong2*)(wr + k);
                ulonglong2 v0 = *(const ulonglong2*)(in0 + k);
                ulonglong2 v1 = *(const ulonglong2*)(in1 + k);
                ffma2(a0, w.x, v0.x); ffma2(a0, w.y, v0.y);
                ffma2(a1, w.x, v1.x); ffma2(a1, w.y, v1.y);
            }
            outv[0] = in0[d] + fmaxf(f2sum(a0) + bv, 0.f);
            outv[1] = in1[d] + fmaxf(f2sum(a1) + bv, 0.f);
        }
#pragma unroll
        for (int c = 0; c < 2; c++) {
            int ln = g + 4 * c;
            float s1 = outv[c], s2 = outv[c] * outv[c];
#pragma unroll
            for (int off = 16; off; off >>= 1) {
                s1 += __shfl_xor_sync(0xFFFFFFFFu, s1, off);
                s2 += __shfl_xor_sync(0xFFFFFFFFu, s2, off);
            }
            if (lane == 0) { sRed[(ln * 2 + wg) * 2] = s1; sRed[(ln * 2 + wg) * 2 + 1] = s2; }
        }
        __syncthreads();
#pragma unroll
        for (int c = 0; c < 2; c++) {
            int ln = g + 4 * c;
            int n = n0 + ln;
            if (n < NN) {
                float s1 = sRed[(ln * 2) * 2] + sRed[(ln * 2 + 1) * 2];
                float s2 = sRed[(ln * 2) * 2 + 1] + sRed[(ln * 2 + 1) * 2 + 1];
                float mu = s1 * (1.f / DD);
                float var = s2 * (1.f / DD) - mu * mu;
                g_x[n * DD + d] = (outv[c] - mu) * rsqrtf(var + 1e-5f) * gv + lbv;
            }
        }
        __syncthreads();
    }
}

// ---------------- edge predictor (EPB=64, tail-guarded) ----------------
#define PRED_SMEM ((DD*W2S + DD + HH + DD + EPB*HH + EPB*DD + EPB*PP + EPB*FE) * 4)

__global__ void __launch_bounds__(512, 1)
pred_kernel(const float* __restrict__ ea,
            const int* __restrict__ src, const int* __restrict__ dst,
            const float* __restrict__ W1, const float* __restrict__ b1,
            const float* __restrict__ W2, const float* __restrict__ b2,
            const float* __restrict__ W3, const float* __restrict__ b3,
            float* __restrict__ out) {
    extern __shared__ float s[];
    float* sW2t = s;                   // [64][132]
    float* sW3  = sW2t + DD * W2S;
    float* sB1  = sW3 + DD;
    float* sB2  = sB1 + HH;
    float* sH1  = sB2 + DD;            // [64][128]
    float* sH2  = sH1 + EPB * HH;      // [64][64]
    float* sPab = sH2 + EPB * DD;      // [64][256]
    float* sEa  = sPab + EPB * PP;     // [64][8]

    const int tid = threadIdx.x;
    for (int i = tid; i < HH * DD; i += 512) { int k = i >> 6, jj = i & 63; sW2t[jj * W2S + k] = W2[i]; }
    if (tid < DD) sW3[tid] = W3[tid];
    if (tid < HH) sB1[tid] = b1[tid];
    if (tid < DD) sB2[tid] = b2[tid];

    const int j = tid & 127, g = tid >> 7;
    const int j2 = tid & 63, eg = tid >> 6;
    const int wid = tid >> 5, lane = tid & 31;
    const float b1v = b1[j], b2v = b2[j2], b3v = b3[0];
    float w1c[8];
#pragma unroll
    for (int f = 0; f < 8; f++) w1c[f] = W1[(2 * DD + f) * HH + j];

    float4 pfa[4], pfb[4];
    float pfe;
    const int sl_t = lane >> 3, sl_f = lane & 7;

#define PRD_PREFETCH(BASE) { \
    _Pragma("unroll") \
    for (int t = 0; t < 4; t++) { \
        int ge = (BASE) + wid * 4 + t; \
        int gc = (ge < NE) ? ge : NE - 1; \
        int sN = src[gc], dN = dst[gc]; \
        pfa[t] = ((const float4*)(g_pab + (size_t)sN * PP))[lane]; \
        pfb[t] = ((const float4*)(g_pab + (size_t)dN * PP + HH))[lane]; } \
    { int ge = (BASE) + wid * 4 + sl_t; \
      int gc = (ge < NE) ? ge : NE - 1; \
      pfe = ea[(size_t)gc * FE + sl_f]; } }

#define PRD_STORE() { \
    _Pragma("unroll") \
    for (int t = 0; t < 4; t++) { \
        int le = wid * 4 + t; \
        ((float4*)(sPab + le * PP))[lane] = pfa[t]; \
        ((float4*)(sPab + le * PP + HH))[lane] = pfb[t]; } \
    sEa[(wid * 4 + sl_t) * FE + sl_f] = pfe; }

    int e0 = blockIdx.x * EPB;
    const int step = gridDim.x * EPB;
    if (e0 < NE) { PRD_PREFETCH(e0); PRD_STORE(); }

    for (; e0 < NE; e0 += step) {
        int enext = e0 + step;
        __syncthreads();

        // phase A: h1 = relu(Pa + Pb + ea@W1c + b1)
#pragma unroll
        for (int c = 0; c < 16; c++) {
            int e = g + 4 * c;
            float hv = sPab[e * PP + j] + sPab[e * PP + HH + j] + b1v;
            float4 a0 = ((const float4*)(sEa + e * FE))[0];
            float4 a1 = ((const float4*)(sEa + e * FE))[1];
            hv = fmaf(a0.x, w1c[0], hv); hv = fmaf(a0.y, w1c[1], hv);
            hv = fmaf(a0.z, w1c[2], hv); hv = fmaf(a0.w, w1c[3], hv);
            hv = fmaf(a1.x, w1c[4], hv); hv = fmaf(a1.y, w1c[5], hv);
            hv = fmaf(a1.z, w1c[6], hv); hv = fmaf(a1.w, w1c[7], hv);
            sH1[e * HH + j] = fmaxf(hv, 0.f);
        }
        if (enext < NE) PRD_PREFETCH(enext);
        __syncthreads();

        // GEMM2: 128 -> 64, E=8 C=1
        u64 acc[8];
#pragma unroll
        for (int c = 0; c < 8; c++) acc[c] = 0ull;
        const float* wr = sW2t + j2 * W2S;
#pragma unroll 2
        for (int k = 0; k < HH; k += 4) {
            ulonglong2 w = *(const ulonglong2*)(wr + k);
#pragma unroll
            for (int c = 0; c < 8; c++) {
                ulonglong2 v = *(const ulonglong2*)(sH1 + (eg * 8 + c) * HH + k);
                ffma2(acc[c], w.x, v.x);
                ffma2(acc[c], w.y, v.y);
            }
        }
#pragma unroll
        for (int c = 0; c < 8; c++)
            sH2[(eg * 8 + c) * DD + j2] = fmaxf(f2sum(acc[c]) + b2v, 0.f);
        __syncthreads();

        // final dot 64 -> 1 + tanh : warp -> its 4 edges (guard write)
#pragma unroll
        for (int t = 0; t < 4; t++) {
            int le = wid * 4 + t, ge = e0 + le;
            float v = sH2[le * DD + lane] * sW3[lane]
                    + sH2[le * DD + 32 + lane] * sW3[32 + lane];
#pragma unroll
            for (int off = 16; off; off >>= 1) v += __shfl_xor_sync(0xFFFFFFFFu, v, off);
            if (lane == 0 && ge < NE) out[ge] = tanhf(v + b3v);
        }
        if (enext < NE) PRD_STORE();
    }
#undef PRD_PREFETCH
#undef PRD_STORE
}

// ---------------- launch ----------------
extern "C" void kernel_launch(void* const* d_in, const int* in_sizes, int n_in,
                              void* d_out, int out_size) {
    const float* node_features = (const float*)d_in[0];
    const float* edge_attr     = (const float*)d_in[1];
    const float* embed_W       = (const float*)d_in[2];
    const float* embed_b       = (const float*)d_in[3];
    const float* msg_W1        = (const float*)d_in[4];
    const float* msg_b1        = (const float*)d_in[5];
    const float* msg_W2        = (const float*)d_in[6];
    const float* msg_b2        = (const float*)d_in[7];
    const float* upd_W         = (const float*)d_in[8];
    const float* upd_b         = (const float*)d_in[9];
    const float* ln_g          = (const float*)d_in[10];
    const float* ln_b          = (const float*)d_in[11];
    const float* pred_W1       = (const float*)d_in[12];
    const float* pred_b1       = (const float*)d_in[13];
    const float* pred_W2       = (const float*)d_in[14];
    const float* pred_b2       = (const float*)d_in[15];
    const float* pred_W3       = (const float*)d_in[16];
    const float* pred_b3       = (const float*)d_in[17];
    const int*   edge_index    = (const int*)d_in[18];
    float* out = (float*)d_out;

    const int* src = edge_index;
    const int* dst = edge_index + NE;

    cudaFuncSetAttribute(msg_kernel,      cudaFuncAttributeMaxDynamicSharedMemorySize, MSG_SMEM);
    cudaFuncSetAttribute(pred_kernel,     cudaFuncAttributeMaxDynamicSharedMemorySize, PRED_SMEM);
    cudaFuncSetAttribute(upd_kernel,      cudaFuncAttributeMaxDynamicSharedMemorySize, UPD_SMEM);
    cudaFuncSetAttribute(node_lin_kernel, cudaFuncAttributeMaxDynamicSharedMemorySize, NL_SMEM);
    cudaFuncSetAttribute(embed_nl_kernel, cudaFuncAttributeMaxDynamicSharedMemorySize, EMB_SMEM);

    init_kernel<<<(NN * HH / 4 + NN / 4 + 255) / 256, 256>>>();
    count_kernel<<<(NE + 255) / 256, 256>>>(dst);
    embed_nl_kernel<<<296, 256, EMB_SMEM>>>(node_features, embed_W, embed_b, msg_W1);

    for (int l = 0; l < LL; l++) {
        // launch index 3 on l=0 -> ncu profiles msg_kernel
        msg_kernel<<<148, 512, MSG_SMEM>>>(edge_attr, src, dst,
                                           msg_W1 + l * EIN * HH, msg_b1 + l * HH,
                                           msg_W2 + l * HH * HH, msg_b2 + l * HH);
        upd_kernel<<<296, 256, UPD_SMEM>>>(upd_W + l * UIN * DD, upd_b + l * DD,
                                           ln_g + l * DD, ln_b + l * DD);
        const float* nextW1 = (l < LL - 1) ? (msg_W1 + (l + 1) * EIN * HH) : pred_W1;
        node_lin_kernel<<<296, 256, NL_SMEM>>>(nextW1);
    }

    pred_kernel<<<148, 512, PRED_SMEM>>>(edge_attr, src, dst,
                                         pred_W1, pred_b1, pred_W2, pred_b2,
                                         pred_W3, pred_b3, out);
}